// round 15
// baseline (speedup 1.0000x reference)
#include <cuda_runtime.h>
#include <cuda_bf16.h>
#include <cstdint>
#include <math.h>

// ---------------- problem constants ----------------
#define BATCH   2
#define SEQLEN  1024
#define DMODEL  1024
#define DSTATE  128
#define DCONV   4
#define HEADDIM 64
#define DINNER  2048
#define NHEADS  32
#define CONVDIM 2304     // DINNER + 2*DSTATE
#define DINPROJ 4384     // 2*DINNER + 2*DSTATE + NHEADS
#define INTERD  2752
#define NTOK    2048     // BATCH*SEQLEN
#define EPSV    1e-6f

// ---------------- fp32 scratch ----------------
__device__ float g_Z  [NTOK * DINPROJ];   // in_proj out; later out_proj split-K partials
__device__ float g_xBC[NTOK * CONVDIM];
__device__ float g_y  [NTOK * DINNER];
__device__ float g_x2 [NTOK * DMODEL];
__device__ float g_g  [NTOK * INTERD];    // gate out; later down split-K partials
__device__ float g_u  [NTOK * INTERD];    // up out

// ---------------- split-bf16 activations ----------------
__device__ __nv_bfloat16 g_x1h[NTOK * DMODEL], g_x1l[NTOK * DMODEL];
__device__ __nv_bfloat16 g_h2h[NTOK * DMODEL], g_h2l[NTOK * DMODEL];
__device__ __nv_bfloat16 g_y2h[NTOK * DINNER], g_y2l[NTOK * DINNER];
__device__ __nv_bfloat16 g_ddh[NTOK * INTERD], g_ddl[NTOK * INTERD];

// ---------------- split-bf16 weights ----------------
__device__ __nv_bfloat16 g_wih[DINPROJ * DMODEL], g_wil[DINPROJ * DMODEL];
__device__ __nv_bfloat16 g_woh[DMODEL * DINNER],  g_wol[DMODEL * DINNER];
__device__ __nv_bfloat16 g_wgh[INTERD * DMODEL],  g_wgl[INTERD * DMODEL];
__device__ __nv_bfloat16 g_wuh[INTERD * DMODEL],  g_wul[INTERD * DMODEL];
__device__ __nv_bfloat16 g_wdh[DMODEL * INTERD],  g_wdl[DMODEL * INTERD];

// ---------------- helpers ----------------
__device__ __forceinline__ uint32_t smem_u32(const void* p) {
    uint32_t a;
    asm("{ .reg .u64 t; cvta.to.shared.u64 t, %1; cvt.u32.u64 %0, t; }" : "=r"(a) : "l"(p));
    return a;
}
__device__ __forceinline__ float blockReduceSum(float v) {
    __shared__ float sb[32];
    int lane = threadIdx.x & 31;
    int w    = threadIdx.x >> 5;
    #pragma unroll
    for (int o = 16; o; o >>= 1) v += __shfl_xor_sync(0xffffffffu, v, o);
    if (lane == 0) sb[w] = v;
    __syncthreads();
    int nw = blockDim.x >> 5;
    float r = (threadIdx.x < (unsigned)nw) ? sb[threadIdx.x] : 0.f;
    if (w == 0) {
        #pragma unroll
        for (int o = 16; o; o >>= 1) r += __shfl_xor_sync(0xffffffffu, r, o);
        if (lane == 0) sb[0] = r;
    }
    __syncthreads();
    return sb[0];
}
__device__ __forceinline__ float siluf(float x) { return x * (1.0f / (1.0f + __expf(-x))); }

__device__ __forceinline__ void ldsm4(uint32_t* r, uint32_t addr) {
    asm volatile("ldmatrix.sync.aligned.m8n8.x4.shared.b16 {%0,%1,%2,%3}, [%4];"
                 : "=r"(r[0]), "=r"(r[1]), "=r"(r[2]), "=r"(r[3]) : "r"(addr));
}
__device__ __forceinline__ void mma16816(float* d, const uint32_t* a, const uint32_t* b) {
    asm volatile(
        "mma.sync.aligned.m16n8k16.row.col.f32.bf16.bf16.f32 "
        "{%0,%1,%2,%3}, {%4,%5,%6,%7}, {%8,%9}, {%0,%1,%2,%3};"
        : "+f"(d[0]), "+f"(d[1]), "+f"(d[2]), "+f"(d[3])
        : "r"(a[0]), "r"(a[1]), "r"(a[2]), "r"(a[3]), "r"(b[0]), "r"(b[1]));
}
__device__ __forceinline__ void split_bf16(float a, float b, uint32_t& hi, uint32_t& lo) {
    __nv_bfloat16 ha = __float2bfloat16(a), hb = __float2bfloat16(b);
    __nv_bfloat16 la = __float2bfloat16(a - __bfloat162float(ha));
    __nv_bfloat16 lb = __float2bfloat16(b - __bfloat162float(hb));
    __nv_bfloat162 th(ha, hb), tl(la, lb);
    hi = *reinterpret_cast<uint32_t*>(&th);
    lo = *reinterpret_cast<uint32_t*>(&tl);
}
__device__ __forceinline__ void cp_async16(uint32_t dst, const void* src, int src_bytes) {
    asm volatile("cp.async.cg.shared.global [%0], [%1], 16, %2;"
                 :: "r"(dst), "l"(src), "r"(src_bytes));
}
__device__ __forceinline__ void cp_commit() { asm volatile("cp.async.commit_group;" ::: "memory"); }
__device__ __forceinline__ void cp_wait2()  { asm volatile("cp.async.wait_group 2;" ::: "memory"); }

// ---------------- merged fp32 -> split-bf16 converter (3 segments) ----------------
__global__ void __launch_bounds__(256)
wsplit3(const float* __restrict__ a, __nv_bfloat16* __restrict__ ah, __nv_bfloat16* __restrict__ al, int na,
        const float* __restrict__ b, __nv_bfloat16* __restrict__ bh, __nv_bfloat16* __restrict__ bl, int nb,
        const float* __restrict__ c, __nv_bfloat16* __restrict__ ch, __nv_bfloat16* __restrict__ cl, int nc) {
    int i = blockIdx.x * 256 + threadIdx.x;
    const float* src; __nv_bfloat16 *oh, *ol; int j;
    if (i < na)                { src = a; oh = ah; ol = al; j = i; }
    else if (i < na + nb)      { src = b; oh = bh; ol = bl; j = i - na; }
    else if (i < na + nb + nc) { src = c; oh = ch; ol = cl; j = i - na - nb; }
    else return;
    float4 v = ((const float4*)src)[j];
    uint32_t h0, l0, h1, l1;
    split_bf16(v.x, v.y, h0, l0);
    split_bf16(v.z, v.w, h1, l1);
    ((uint2*)oh)[j] = make_uint2(h0, h1);
    ((uint2*)ol)[j] = make_uint2(l0, l1);
}

// ================= split-bf16 tensor-core GEMM: 128x128 tile, 4-stage KC=16 pipeline =================
// Modes: dual-weight (Wh2 != null): blockIdx.z selects {Wh,Cf} vs {Wh2,Cf2}
//        split-K (kParts>1): blockIdx.z = K-part, output partial at Cf + z*M*N
#define KC 16
#define ROWB 24                                // bf16 row stride (48B) -> conflict-free phases
#define ARR_B   (128 * ROWB * 2)               // 6144 B per array
#define OFF_AH  0
#define OFF_AL  (ARR_B)
#define OFF_BH  (2 * ARR_B)
#define OFF_BL  (3 * ARR_B)
#define STAGE_B (4 * ARR_B)                    // 24576 B
#define NSTAGE  4
#define GEMM_SMEM (NSTAGE * STAGE_B)           // 98304 B

extern __shared__ __align__(16) __nv_bfloat16 dsm[];

__global__ void __launch_bounds__(256, 2)
gemm_bf16(const __nv_bfloat16* __restrict__ Ah_, const __nv_bfloat16* __restrict__ Al_,
          const __nv_bfloat16* __restrict__ Wh_, const __nv_bfloat16* __restrict__ Wl_,
          const __nv_bfloat16* __restrict__ Wh2_, const __nv_bfloat16* __restrict__ Wl2_,
          float* __restrict__ Cf, float* __restrict__ Cf2,
          int M, int N, int K, int kParts) {
    uint32_t sbase = smem_u32(dsm);
    int tid  = threadIdx.x;
    int wid  = tid >> 5;
    int lane = tid & 31;
    int wr   = wid & 3;
    int wc   = wid >> 2;
    int row0 = blockIdx.y * 128;
    int col0 = blockIdx.x * 128;

    int kbase = 0;
    float* outp = Cf;
    if (kParts > 1) {
        kbase = blockIdx.z * (K / kParts);
        outp  = Cf + (size_t)blockIdx.z * M * N;
    } else if (Wh2_ && blockIdx.z == 1) {
        Wh_ = Wh2_; Wl_ = Wl2_; outp = Cf2;
    }
    int NC = (K / kParts) / KC;

    float acc[2][8][4];
    #pragma unroll
    for (int mt = 0; mt < 2; mt++)
        #pragma unroll
        for (int nt = 0; nt < 8; nt++)
            #pragma unroll
            for (int q = 0; q < 4; q++) acc[mt][nt][q] = 0.f;

    // ldmatrix lane address components (row stride 48B)
    int aRow  = wr * 32 + (lane & 15);
    int aColB = ((lane >> 4) & 1) * 16;
    int bRow  = wc * 64 + (lane & 7) + ((lane >> 4) & 1) * 8;
    int bColB = ((lane >> 3) & 1) * 16;

    // cp.async: 1 x 16B per array per thread per chunk (256 thr = 128 rows x 2 segs)
    int crow = tid >> 1;
    int cce  = (tid & 1) * 8;
    int wrow = col0 + crow;
    int bsz   = (wrow < N) ? 16 : 0;
    int bsafe = (wrow < N) ? wrow : 0;

    auto issue = [&](int c, int st) {
        uint32_t base = sbase + st * STAGE_B;
        uint32_t doff = (uint32_t)(crow * ROWB + cce) * 2;
        size_t goA = (size_t)(row0 + crow) * K + kbase + c * KC + cce;
        cp_async16(base + OFF_AH + doff, Ah_ + goA, 16);
        cp_async16(base + OFF_AL + doff, Al_ + goA, 16);
        size_t goW = (size_t)bsafe * K + kbase + c * KC + cce;
        cp_async16(base + OFF_BH + doff, Wh_ + goW, bsz);
        cp_async16(base + OFF_BL + doff, Wl_ + goW, bsz);
    };

    // prologue: fill 3 stages
    #pragma unroll
    for (int c = 0; c < NSTAGE - 1; c++) { issue(c, c); cp_commit(); }

    for (int c = 0; c < NC; c++) {
        cp_wait2();            // groups <= c complete  -> chunk c resident
        __syncthreads();       // all warps done reading stage (c-1)&3 (= target of c+3)
        if (c + NSTAGE - 1 < NC) issue(c + NSTAGE - 1, (c + NSTAGE - 1) & (NSTAGE - 1));
        cp_commit();           // unconditional: keeps group<->chunk numbering aligned

        uint32_t base = sbase + (c & (NSTAGE - 1)) * STAGE_B;

        uint32_t Am[2][4], Al2[2][4];
        #pragma unroll
        for (int mt = 0; mt < 2; mt++) {
            uint32_t off = (uint32_t)((aRow + mt * 16) * (ROWB * 2) + aColB);
            ldsm4(Am[mt],  base + OFF_AH + off);
            ldsm4(Al2[mt], base + OFF_AL + off);
        }
        // software-pipelined B fragments across ntp
        uint32_t Bb[2][2][4];
        {
            uint32_t off0 = (uint32_t)(bRow * (ROWB * 2) + bColB);
            ldsm4(Bb[0][0], base + OFF_BH + off0);
            ldsm4(Bb[0][1], base + OFF_BL + off0);
        }
        #pragma unroll
        for (int ntp = 0; ntp < 4; ntp++) {
            int cb = ntp & 1, nb = cb ^ 1;
            if (ntp < 3) {
                uint32_t off = (uint32_t)((bRow + (ntp + 1) * 16) * (ROWB * 2) + bColB);
                ldsm4(Bb[nb][0], base + OFF_BH + off);
                ldsm4(Bb[nb][1], base + OFF_BL + off);
            }
            #pragma unroll
            for (int mt = 0; mt < 2; mt++) {
                mma16816(acc[mt][ntp * 2 + 0], Am[mt], &Bb[cb][0][0]);
                mma16816(acc[mt][ntp * 2 + 1], Am[mt], &Bb[cb][0][2]);
            }
            #pragma unroll
            for (int mt = 0; mt < 2; mt++) {
                mma16816(acc[mt][ntp * 2 + 0], Am[mt], &Bb[cb][1][0]);
                mma16816(acc[mt][ntp * 2 + 1], Am[mt], &Bb[cb][1][2]);
            }
            #pragma unroll
            for (int mt = 0; mt < 2; mt++) {
                mma16816(acc[mt][ntp * 2 + 0], Al2[mt], &Bb[cb][0][0]);
                mma16816(acc[mt][ntp * 2 + 1], Al2[mt], &Bb[cb][0][2]);
            }
        }
    }

    // ---- epilogue: plain fp32 stores ----
    __syncthreads();
    int gid = lane >> 2;
    int tig = lane & 3;
    #pragma unroll
    for (int mt = 0; mt < 2; mt++) {
        int r0 = row0 + wr * 32 + mt * 16 + gid;
        #pragma unroll
        for (int nt = 0; nt < 8; nt++) {
            int col = col0 + wc * 64 + nt * 8 + tig * 2;
            if (col < N) {
                *(float2*)(outp + (size_t)r0 * N + col) =
                    make_float2(acc[mt][nt][0], acc[mt][nt][1]);
                *(float2*)(outp + (size_t)(r0 + 8) * N + col) =
                    make_float2(acc[mt][nt][2], acc[mt][nt][3]);
            }
        }
    }
}

// ---------------- rmsnorm over D=1024, writes split-bf16 ----------------
__global__ void __launch_bounds__(256) rmsnorm1024(const float* __restrict__ x,
                                                   const float* __restrict__ w,
                                                   __nv_bfloat16* __restrict__ oh,
                                                   __nv_bfloat16* __restrict__ ol) {
    int tok = blockIdx.x;
    int tid = threadIdx.x;
    const float4* xp = (const float4*)(x + (size_t)tok * DMODEL);
    float4 v = xp[tid];
    float ss = v.x * v.x + v.y * v.y + v.z * v.z + v.w * v.w;
    ss = blockReduceSum(ss);
    float rs = rsqrtf(ss * (1.0f / DMODEL) + EPSV);
    float4 wv = ((const float4*)w)[tid];
    float4 o;
    o.x = v.x * rs * wv.x; o.y = v.y * rs * wv.y;
    o.z = v.z * rs * wv.z; o.w = v.w * rs * wv.w;
    uint32_t h0, l0, h1, l1;
    split_bf16(o.x, o.y, h0, l0);
    split_bf16(o.z, o.w, h1, l1);
    ((uint2*)(oh + (size_t)tok * DMODEL))[tid] = make_uint2(h0, h1);
    ((uint2*)(ol + (size_t)tok * DMODEL))[tid] = make_uint2(l0, l1);
}

// ---------------- rmsnorm of (hidden + p0 + p1): writes x2 (fp32) + split-bf16 ----------------
__global__ void __launch_bounds__(256) rmsnorm_sum3(const float* __restrict__ hid,
                                                    const float* __restrict__ p0,
                                                    const float* __restrict__ p1,
                                                    const float* __restrict__ w,
                                                    float* __restrict__ x2out,
                                                    __nv_bfloat16* __restrict__ oh,
                                                    __nv_bfloat16* __restrict__ ol) {
    int tok = blockIdx.x;
    int tid = threadIdx.x;
    size_t off = (size_t)tok * DMODEL;
    float4 a = ((const float4*)(hid + off))[tid];
    float4 b = ((const float4*)(p0  + off))[tid];
    float4 c = ((const float4*)(p1  + off))[tid];
    float4 v;
    v.x = a.x + b.x + c.x; v.y = a.y + b.y + c.y;
    v.z = a.z + b.z + c.z; v.w = a.w + b.w + c.w;
    ((float4*)(x2out + off))[tid] = v;
    float ss = v.x * v.x + v.y * v.y + v.z * v.z + v.w * v.w;
    ss = blockReduceSum(ss);
    float rs = rsqrtf(ss * (1.0f / DMODEL) + EPSV);
    float4 wv = ((const float4*)w)[tid];
    float4 o;
    o.x = v.x * rs * wv.x; o.y = v.y * rs * wv.y;
    o.z = v.z * rs * wv.z; o.w = v.w * rs * wv.w;
    uint32_t h0, l0, h1, l1;
    split_bf16(o.x, o.y, h0, l0);
    split_bf16(o.z, o.w, h1, l1);
    ((uint2*)(oh + off))[tid] = make_uint2(h0, h1);
    ((uint2*)(ol + off))[tid] = make_uint2(l0, l1);
}

// ---------------- final residual: out = x2 + p0 + p1 ----------------
__global__ void __launch_bounds__(256) add3(const float* __restrict__ x2,
                                            const float* __restrict__ p0,
                                            const float* __restrict__ p1,
                                            float* __restrict__ out, int n4) {
    int i = blockIdx.x * 256 + threadIdx.x;
    if (i < n4) {
        float4 a = ((const float4*)x2)[i];
        float4 b = ((const float4*)p0)[i];
        float4 c = ((const float4*)p1)[i];
        float4 v;
        v.x = a.x + b.x + c.x; v.y = a.y + b.y + c.y;
        v.z = a.z + b.z + c.z; v.w = a.w + b.w + c.w;
        ((float4*)out)[i] = v;
    }
}

// ---------------- swiglu + split: dd = split_bf16(silu(g) * u) ----------------
__global__ void __launch_bounds__(256) swiglu_split(const float* __restrict__ g,
                                                    const float* __restrict__ u,
                                                    __nv_bfloat16* __restrict__ oh,
                                                    __nv_bfloat16* __restrict__ ol, int n4) {
    int i = blockIdx.x * 256 + threadIdx.x;
    if (i < n4) {
        float4 gv = ((const float4*)g)[i];
        float4 uv = ((const float4*)u)[i];
        float4 v;
        v.x = siluf(gv.x) * uv.x; v.y = siluf(gv.y) * uv.y;
        v.z = siluf(gv.z) * uv.z; v.w = siluf(gv.w) * uv.w;
        uint32_t h0, l0, h1, l1;
        split_bf16(v.x, v.y, h0, l0);
        split_bf16(v.z, v.w, h1, l1);
        ((uint2*)oh)[i] = make_uint2(h0, h1);
        ((uint2*)ol)[i] = make_uint2(l0, l1);
    }
}

// ---------------- gated rmsnorm over D_INNER=2048, writes split-bf16 ----------------
__global__ void __launch_bounds__(256) gated_rmsnorm(const float* __restrict__ y,
                                                     const float* __restrict__ Z,
                                                     const float* __restrict__ w,
                                                     __nv_bfloat16* __restrict__ oh,
                                                     __nv_bfloat16* __restrict__ ol) {
    int tok = blockIdx.x;
    int tid = threadIdx.x;
    const float4* yp = (const float4*)(y + (size_t)tok * DINNER);
    const float4* zp = (const float4*)(Z + (size_t)tok * DINPROJ);
    float4 v[2];
    float ss = 0.f;
    #pragma unroll
    for (int q = 0; q < 2; q++) {
        float4 yv = yp[tid + q * 256];
        float4 zv = zp[tid + q * 256];
        float4 t;
        t.x = yv.x * siluf(zv.x); t.y = yv.y * siluf(zv.y);
        t.z = yv.z * siluf(zv.z); t.w = yv.w * siluf(zv.w);
        v[q] = t;
        ss += t.x * t.x + t.y * t.y + t.z * t.z + t.w * t.w;
    }
    ss = blockReduceSum(ss);
    float rs = rsqrtf(ss * (1.0f / DINNER) + EPSV);
    #pragma unroll
    for (int q = 0; q < 2; q++) {
        float4 wv = ((const float4*)w)[tid + q * 256];
        float4 o;
        o.x = v[q].x * rs * wv.x; o.y = v[q].y * rs * wv.y;
        o.z = v[q].z * rs * wv.z; o.w = v[q].w * rs * wv.w;
        uint32_t h0, l0, h1, l1;
        split_bf16(o.x, o.y, h0, l0);
        split_bf16(o.z, o.w, h1, l1);
        ((uint2*)(oh + (size_t)tok * DINNER))[tid + q * 256] = make_uint2(h0, h1);
        ((uint2*)(ol + (size_t)tok * DINNER))[tid + q * 256] = make_uint2(l0, l1);
    }
}

// ---------------- causal depthwise conv (width 4) + silu ----------------
__global__ void __launch_bounds__(256) conv_silu(const float* __restrict__ Z,
                                                 const float* __restrict__ cw,
                                                 const float* __restrict__ cb,
                                                 float* __restrict__ out) {
    int c   = blockIdx.x * 256 + threadIdx.x;
    int tok = blockIdx.y;
    if (c >= CONVDIM) return;
    int l = tok & (SEQLEN - 1);
    float w0 = cw[c * 4 + 0], w1 = cw[c * 4 + 1], w2 = cw[c * 4 + 2], w3 = cw[c * 4 + 3];
    const float* zc = Z + (size_t)tok * DINPROJ + DINNER + c;
    float acc = cb[c];
    acc += zc[0] * w3;
    if (l >= 1) acc += zc[-(ptrdiff_t)DINPROJ]     * w2;
    if (l >= 2) acc += zc[-(ptrdiff_t)DINPROJ * 2] * w1;
    if (l >= 3) acc += zc[-(ptrdiff_t)DINPROJ * 3] * w0;
    out[(size_t)tok * CONVDIM + c] = siluf(acc);
}

// ---------------- sequential SSM scan: 8-way p-split, 512 blocks ----------------
__global__ void __launch_bounds__(128) ssm_scan(const float* __restrict__ xBC,
                                                const float* __restrict__ Z,
                                                const float* __restrict__ dt_bias,
                                                const float* __restrict__ A_log,
                                                const float* __restrict__ Dp,
                                                float* __restrict__ y) {
    int bid   = blockIdx.x;          // 512 = b(2) * h(32) * oct(8)
    int b     = bid >> 8;
    int h     = (bid >> 3) & 31;
    int oct   = bid & 7;
    int pbase = oct * 8;
    int t     = threadIdx.x;

    __shared__ float s_dtx[2][2][8];
    __shared__ float s_x[2][2][8];
    __shared__ float s_red[2][8][144];

    float hs[8];
    #pragma unroll
    for (int p = 0; p < 8; p++) hs[p] = 0.f;

    float Ahv = -__expf(A_log[h]);
    float dbh = dt_bias[h];
    float Dh  = Dp[h];
    int   rp  = t >> 4;
    int   ri  = t & 15;

    const float* xrow  = xBC + (size_t)b * SEQLEN * CONVDIM;
    const float* dtrow = Z + (size_t)b * SEQLEN * DINPROJ + (DINPROJ - NHEADS) + h;
    float*       yrow  = y + (size_t)b * SEQLEN * DINNER + h * HEADDIM + pbase;

    float Bv[2], Cv[2], dAc[2];
    float B1[2], C1[2], dt1[2], x1v[2];

    #pragma unroll
    for (int q = 0; q < 2; q++) {
        const float* xr = xrow + (size_t)q * CONVDIM;
        Bv[q] = xr[DINNER + t];
        Cv[q] = xr[DINNER + DSTATE + t];
        float dts = dtrow[(size_t)q * DINPROJ] + dbh;
        float dtv = (dts > 20.f) ? dts : __logf(1.f + __expf(dts));
        dAc[q] = __expf(dtv * Ahv);
        if (t < 8) {
            float x0 = xr[h * HEADDIM + pbase + t];
            s_dtx[0][q][t] = dtv * x0; s_x[0][q][t] = x0;
        }
    }
    #pragma unroll
    for (int q = 0; q < 2; q++) {
        const float* xr = xrow + (size_t)(2 + q) * CONVDIM;
        B1[q]  = xr[DINNER + t];
        C1[q]  = xr[DINNER + DSTATE + t];
        dt1[q] = dtrow[(size_t)(2 + q) * DINPROJ];
        x1v[q] = (t < 8) ? xr[h * HEADDIM + pbase + t] : 0.f;
    }
    __syncthreads();

    int cur = 0;
    for (int i = 0; i < SEQLEN / 2; i++) {
        int nxt = cur ^ 1;
        float dAn[2] = {0.f, 0.f};
        if (i < SEQLEN / 2 - 1) {
            #pragma unroll
            for (int q = 0; q < 2; q++) {
                float dts = dt1[q] + dbh;
                float dtv = (dts > 20.f) ? dts : __logf(1.f + __expf(dts));
                dAn[q] = __expf(dtv * Ahv);
                if (t < 8) { s_dtx[nxt][q][t] = dtv * x1v[q]; s_x[nxt][q][t] = x1v[q]; }
            }
        }
        #pragma unroll
        for (int q = 0; q < 2; q++) {
            float dAq = dAc[q], Bq = Bv[q], Cq = Cv[q];
            #pragma unroll
            for (int p = 0; p < 8; p++) {
                hs[p] = fmaf(hs[p], dAq, s_dtx[cur][q][p] * Bq);
                s_red[q][p][t] = hs[p] * Cq;
            }
        }
        __syncthreads();

        #pragma unroll
        for (int q = 0; q < 2; q++) {
            float sum = 0.f;
            #pragma unroll
            for (int k = 0; k < 8; k++) sum += s_red[q][rp][k * 16 + ri];
            #pragma unroll
            for (int o = 8; o; o >>= 1) sum += __shfl_xor_sync(0xffffffffu, sum, o, 16);
            if (ri == 0)
                yrow[(size_t)(2 * i + q) * DINNER + rp] = sum + Dh * s_x[cur][q][rp];
        }

        dAc[0] = dAn[0]; dAc[1] = dAn[1];
        Bv[0] = B1[0]; Bv[1] = B1[1];
        Cv[0] = C1[0]; Cv[1] = C1[1];
        if (i < SEQLEN / 2 - 2) {
            #pragma unroll
            for (int q = 0; q < 2; q++) {
                int s = 2 * i + 4 + q;
                const float* xr = xrow + (size_t)s * CONVDIM;
                B1[q]  = xr[DINNER + t];
                C1[q]  = xr[DINNER + DSTATE + t];
                dt1[q] = dtrow[(size_t)s * DINPROJ];
                x1v[q] = (t < 8) ? xr[h * HEADDIM + pbase + t] : 0.f;
            }
        }
        __syncthreads();
        cur = nxt;
    }
}

// ---------------- launch ----------------
extern "C" void kernel_launch(void* const* d_in, const int* in_sizes, int n_in,
                              void* d_out, int out_size) {
    const float* hidden     = (const float*)d_in[0];
    const float* norm_w     = (const float*)d_in[1];
    const float* in_proj_w  = (const float*)d_in[2];
    const float* conv_w     = (const float*)d_in[3];
    const float* conv_b     = (const float*)d_in[4];
    const float* dt_bias    = (const float*)d_in[5];
    const float* A_log      = (const float*)d_in[6];
    const float* Dvec       = (const float*)d_in[7];
    const float* ssm_norm_w = (const float*)d_in[8];
    const float* out_proj_w = (const float*)d_in[9];
    const float* post_norm_w= (const float*)d_in[10];
    const float* gate_w     = (const float*)d_in[11];
    const float* up_w       = (const float*)d_in[12];
    const float* down_w     = (const float*)d_in[13];
    float* out = (float*)d_out;

    float *Z, *xBC, *y, *x2, *gg, *uu;
    cudaGetSymbolAddress((void**)&Z,   g_Z);
    cudaGetSymbolAddress((void**)&xBC, g_xBC);
    cudaGetSymbolAddress((void**)&y,   g_y);
    cudaGetSymbolAddress((void**)&x2,  g_x2);
    cudaGetSymbolAddress((void**)&gg,  g_g);
    cudaGetSymbolAddress((void**)&uu,  g_u);

    __nv_bfloat16 *x1h, *x1l, *h2h, *h2l, *y2h, *y2l, *ddh, *ddl;
    cudaGetSymbolAddress((void**)&x1h, g_x1h); cudaGetSymbolAddress((void**)&x1l, g_x1l);
    cudaGetSymbolAddress((void**)&h2h, g_h2h); cudaGetSymbolAddress((void**)&h2l, g_h2l);
    cudaGetSymbolAddress((void**)&y2h, g_y2h); cudaGetSymbolAddress((void**)&y2l, g_y2l);
    cudaGetSymbolAddress((void**)&ddh, g_ddh); cudaGetSymbolAddress((void**)&ddl, g_ddl);

    __nv_bfloat16 *wih, *wil, *woh, *wol, *wgh, *wgl, *wuh, *wul, *wdh, *wdl;
    cudaGetSymbolAddress((void**)&wih, g_wih); cudaGetSymbolAddress((void**)&wil, g_wil);
    cudaGetSymbolAddress((void**)&woh, g_woh); cudaGetSymbolAddress((void**)&wol, g_wol);
    cudaGetSymbolAddress((void**)&wgh, g_wgh); cudaGetSymbolAddress((void**)&wgl, g_wgl);
    cudaGetSymbolAddress((void**)&wuh, g_wuh); cudaGetSymbolAddress((void**)&wul, g_wul);
    cudaGetSymbolAddress((void**)&wdh, g_wdh); cudaGetSymbolAddress((void**)&wdl, g_wdl);

    cudaFuncSetAttribute(gemm_bf16, cudaFuncAttributeMaxDynamicSharedMemorySize, GEMM_SMEM);

    const int nIn = DINPROJ * DMODEL / 4, nOut = DMODEL * DINNER / 4;
    const int nGU = INTERD * DMODEL / 4,  nDn  = DMODEL * INTERD / 4;

    // 0,1: weight pre-conversion
    wsplit3<<<(nIn + nOut + nGU + 255) / 256, 256>>>(
        in_proj_w, wih, wil, nIn, out_proj_w, woh, wol, nOut, gate_w, wgh, wgl, nGU);
    wsplit3<<<(nGU + nDn + 255) / 256, 256>>>(
        up_w, wuh, wul, nGU, down_w, wdh, wdl, nDn, nullptr, nullptr, nullptr, 0);

    // 2: pre-norm
    rmsnorm1024<<<NTOK, 256>>>(hidden, norm_w, x1h, x1l);
    // 3: in_proj -> Z
    gemm_bf16<<<dim3((DINPROJ + 127) / 128, NTOK / 128, 1), 256, GEMM_SMEM>>>(
        x1h, x1l, wih, wil, nullptr, nullptr, Z, nullptr, NTOK, DINPROJ, DMODEL, 1);
    // 4: causal conv + silu
    conv_silu<<<dim3((CONVDIM + 255) / 256, NTOK), 256>>>(Z, conv_w, conv_b, xBC);
    // 5: SSM scan (+ D skip)
    ssm_scan<<<512, 128>>>(xBC, Z, dt_bias, A_log, Dvec, y);
    // 6: gated rmsnorm -> y2 split  (Z z-gate consumed; Z dead after)
    gated_rmsnorm<<<NTOK, 256>>>(y, Z, ssm_norm_w, y2h, y2l);
    // 7: out_proj split-K2 -> partials in Z scratch
    gemm_bf16<<<dim3(DMODEL / 128, NTOK / 128, 2), 256, GEMM_SMEM>>>(
        y2h, y2l, woh, wol, nullptr, nullptr, Z, nullptr, NTOK, DMODEL, DINNER, 2);
    // 8: x2 = hidden + p0 + p1; post-norm -> h2 split
    rmsnorm_sum3<<<NTOK, 256>>>(hidden, Z, Z + (size_t)NTOK * DMODEL, post_norm_w,
                                x2, h2h, h2l);
    // 9: gate & up fused in one launch (z selects weight/output)
    gemm_bf16<<<dim3((INTERD + 127) / 128, NTOK / 128, 2), 256, GEMM_SMEM>>>(
        h2h, h2l, wgh, wgl, wuh, wul, gg, uu, NTOK, INTERD, DMODEL, 1);
    // 10: swiglu + split -> dd
    swiglu_split<<<(NTOK * INTERD / 4 + 255) / 256, 256>>>(
        gg, uu, ddh, ddl, NTOK * INTERD / 4);
    // 11: down proj split-K2 -> partials in gg scratch
    gemm_bf16<<<dim3(DMODEL / 128, NTOK / 128, 2), 256, GEMM_SMEM>>>(
        ddh, ddl, wdh, wdl, nullptr, nullptr, gg, nullptr, NTOK, DMODEL, INTERD, 2);
    // 12: out = x2 + p0 + p1
    add3<<<(NTOK * DMODEL / 4 + 255) / 256, 256>>>(
        x2, gg, gg + (size_t)NTOK * DMODEL, out, NTOK * DMODEL / 4);
}

// round 16
// speedup vs baseline: 1.1747x; 1.1747x over previous
#include <cuda_runtime.h>
#include <cuda_bf16.h>
#include <cstdint>
#include <math.h>

// ---------------- problem constants ----------------
#define BATCH   2
#define SEQLEN  1024
#define DMODEL  1024
#define DSTATE  128
#define DCONV   4
#define HEADDIM 64
#define DINNER  2048
#define NHEADS  32
#define CONVDIM 2304     // DINNER + 2*DSTATE
#define DINPROJ 4384     // 2*DINNER + 2*DSTATE + NHEADS
#define INTERD  2752
#define NTOK    2048     // BATCH*SEQLEN
#define EPSV    1e-6f

// ---------------- fp32 scratch ----------------
__device__ float g_Z  [NTOK * DINPROJ];   // in_proj out; later out_proj split-K partials
__device__ float g_xBC[NTOK * CONVDIM];
__device__ float g_y  [NTOK * DINNER];
__device__ float g_x2 [NTOK * DMODEL];
__device__ float g_g  [NTOK * INTERD];    // gate out; later down split-K partials
__device__ float g_u  [NTOK * INTERD];    // up out

// ---------------- tf32-rounded fp32 activations ----------------
__device__ float g_x1r[NTOK * DMODEL];
__device__ float g_h2r[NTOK * DMODEL];
__device__ float g_y2r[NTOK * DINNER];
__device__ float g_ddr[NTOK * INTERD];

// ---------------- tf32-rounded fp32 weights ----------------
__device__ float g_wir[DINPROJ * DMODEL];
__device__ float g_wor[DMODEL * DINNER];
__device__ float g_wgr[INTERD * DMODEL];
__device__ float g_wur[INTERD * DMODEL];
__device__ float g_wdr[DMODEL * INTERD];

// ---------------- helpers ----------------
__device__ __forceinline__ uint32_t smem_u32(const void* p) {
    uint32_t a;
    asm("{ .reg .u64 t; cvta.to.shared.u64 t, %1; cvt.u32.u64 %0, t; }" : "=r"(a) : "l"(p));
    return a;
}
__device__ __forceinline__ float blockReduceSum(float v) {
    __shared__ float sb[32];
    int lane = threadIdx.x & 31;
    int w    = threadIdx.x >> 5;
    #pragma unroll
    for (int o = 16; o; o >>= 1) v += __shfl_xor_sync(0xffffffffu, v, o);
    if (lane == 0) sb[w] = v;
    __syncthreads();
    int nw = blockDim.x >> 5;
    float r = (threadIdx.x < (unsigned)nw) ? sb[threadIdx.x] : 0.f;
    if (w == 0) {
        #pragma unroll
        for (int o = 16; o; o >>= 1) r += __shfl_xor_sync(0xffffffffu, r, o);
        if (lane == 0) sb[0] = r;
    }
    __syncthreads();
    return sb[0];
}
__device__ __forceinline__ float siluf(float x) { return x * (1.0f / (1.0f + __expf(-x))); }

__device__ __forceinline__ float tf32r(float x) {
    uint32_t r;
    asm("cvt.rna.tf32.f32 %0, %1;" : "=r"(r) : "f"(x));
    return __uint_as_float(r);
}
__device__ __forceinline__ void mma_tf32(float* d, const uint32_t* a, uint32_t b0, uint32_t b1) {
    asm volatile(
        "mma.sync.aligned.m16n8k8.row.col.f32.tf32.tf32.f32 "
        "{%0,%1,%2,%3}, {%4,%5,%6,%7}, {%8,%9}, {%0,%1,%2,%3};"
        : "+f"(d[0]), "+f"(d[1]), "+f"(d[2]), "+f"(d[3])
        : "r"(a[0]), "r"(a[1]), "r"(a[2]), "r"(a[3]), "r"(b0), "r"(b1));
}
__device__ __forceinline__ void cp_async16(uint32_t dst, const void* src, int src_bytes) {
    asm volatile("cp.async.cg.shared.global [%0], [%1], 16, %2;"
                 :: "r"(dst), "l"(src), "r"(src_bytes));
}
__device__ __forceinline__ void cp_commit() { asm volatile("cp.async.commit_group;" ::: "memory"); }
__device__ __forceinline__ void cp_wait0()  { asm volatile("cp.async.wait_group 0;" ::: "memory"); }

// ---------------- merged fp32 -> tf32-rounded converter (3 segments) ----------------
__global__ void __launch_bounds__(256)
wcvt3(const float* __restrict__ a, float* __restrict__ ao, int na,
      const float* __restrict__ b, float* __restrict__ bo, int nb,
      const float* __restrict__ c, float* __restrict__ co, int nc) {
    int i = blockIdx.x * 256 + threadIdx.x;
    const float* src; float* dst; int j;
    if (i < na)                { src = a; dst = ao; j = i; }
    else if (i < na + nb)      { src = b; dst = bo; j = i - na; }
    else if (i < na + nb + nc) { src = c; dst = co; j = i - na - nb; }
    else return;
    float4 v = ((const float4*)src)[j];
    float4 o;
    o.x = tf32r(v.x); o.y = tf32r(v.y); o.z = tf32r(v.z); o.w = tf32r(v.w);
    ((float4*)dst)[j] = o;
}

// ================= tf32 single-pass tensor-core GEMM: 128x128 tile, KC=32, 2-stage =================
// Modes: dual-weight (W2 != null): blockIdx.z selects {W,Cf} vs {W2,Cf2}
//        split-K (kParts>1): blockIdx.z = K-part, output partial at Cf + z*M*N
#define KC 32
#define PADK 36                                // fp32 row stride (144B): banks 4g+t conflict-free
#define ARR_F   (128 * PADK)                   // 4608 floats per array
#define OFF_A   0
#define OFF_B   ARR_F
#define STAGE_F (2 * ARR_F)                    // 9216 floats = 36864 B
#define STAGE_BY (STAGE_F * 4)
#define GEMM_SMEM (2 * STAGE_BY)               // 73728 B

extern __shared__ __align__(16) uint32_t usm[];

__global__ void __launch_bounds__(256, 2)
gemm_tf32(const float* __restrict__ A_, const float* __restrict__ W_,
          const float* __restrict__ W2_,
          float* __restrict__ Cf, float* __restrict__ Cf2,
          int M, int N, int K, int kParts) {
    uint32_t sbase = smem_u32(usm);
    int tid  = threadIdx.x;
    int wid  = tid >> 5;
    int lane = tid & 31;
    int wr   = wid & 3;          // 4 warps along M (32 rows)
    int wc   = wid >> 2;         // 2 warps along N (64 cols)
    int g    = lane >> 2;        // groupID 0..7
    int t    = lane & 3;         // threadID_in_group
    int row0 = blockIdx.y * 128;
    int col0 = blockIdx.x * 128;

    int kbase = 0;
    float* outp = Cf;
    if (kParts > 1) {
        kbase = blockIdx.z * (K / kParts);
        outp  = Cf + (size_t)blockIdx.z * M * N;
    } else if (W2_ && blockIdx.z == 1) {
        W_ = W2_; outp = Cf2;
    }
    int NC = (K / kParts) / KC;

    float acc[2][8][4];
    #pragma unroll
    for (int mt = 0; mt < 2; mt++)
        #pragma unroll
        for (int nt = 0; nt < 8; nt++)
            #pragma unroll
            for (int q = 0; q < 4; q++) acc[mt][nt][q] = 0.f;

    // cp.async slots: 4 granules(16B) per array per thread per chunk
    int rowL[4], kcL[4];
    #pragma unroll
    for (int s = 0; s < 4; s++) {
        int idx = s * 256 + tid;
        rowL[s] = idx >> 3;          // 0..127
        kcL[s]  = (idx & 7) * 4;     // float offset 0..28
    }
    int bsz[4], bsafe[4];
    #pragma unroll
    for (int s = 0; s < 4; s++) {
        int wrow = col0 + rowL[s];
        bsz[s]   = (wrow < N) ? 16 : 0;
        bsafe[s] = (wrow < N) ? wrow : 0;
    }

    auto issue = [&](int c, int st) {
        uint32_t base = sbase + st * STAGE_BY;
        #pragma unroll
        for (int s = 0; s < 4; s++) {
            uint32_t doff = (uint32_t)(rowL[s] * PADK + kcL[s]) * 4;
            size_t goA = (size_t)(row0 + rowL[s]) * K + kbase + c * KC + kcL[s];
            cp_async16(base + doff, A_ + goA, 16);
            size_t goW = (size_t)bsafe[s] * K + kbase + c * KC + kcL[s];
            cp_async16(base + OFF_B * 4 + doff, W_ + goW, bsz[s]);
        }
    };

    issue(0, 0);
    cp_commit();

    for (int c = 0; c < NC; c++) {
        cp_wait0();
        __syncthreads();
        if (c + 1 < NC) { issue(c + 1, (c + 1) & 1); cp_commit(); }

        const uint32_t stoff = (c & 1) * STAGE_F;
        const uint32_t* sA = usm + stoff + OFF_A;
        const uint32_t* sB = usm + stoff + OFF_B;

        #pragma unroll
        for (int k8 = 0; k8 < 4; k8++) {
            int kb = k8 * 8;
            // A fragments (m16n8k8 tf32 layout)
            uint32_t Af[2][4];
            #pragma unroll
            for (int mt = 0; mt < 2; mt++) {
                int r = wr * 32 + mt * 16 + g;
                Af[mt][0] = sA[r * PADK + kb + t];
                Af[mt][1] = sA[(r + 8) * PADK + kb + t];
                Af[mt][2] = sA[r * PADK + kb + t + 4];
                Af[mt][3] = sA[(r + 8) * PADK + kb + t + 4];
            }
            // B fragments, software-pipelined over nt
            int n0 = wc * 64 + g;
            uint32_t b0c = sB[n0 * PADK + kb + t];
            uint32_t b1c = sB[n0 * PADK + kb + t + 4];
            #pragma unroll
            for (int nt = 0; nt < 8; nt++) {
                uint32_t b0n = 0, b1n = 0;
                if (nt < 7) {
                    int n = n0 + (nt + 1) * 8;
                    b0n = sB[n * PADK + kb + t];
                    b1n = sB[n * PADK + kb + t + 4];
                }
                mma_tf32(acc[0][nt], Af[0], b0c, b1c);
                mma_tf32(acc[1][nt], Af[1], b0c, b1c);
                b0c = b0n; b1c = b1n;
            }
        }
    }

    // ---- epilogue: plain fp32 stores ----
    __syncthreads();
    #pragma unroll
    for (int mt = 0; mt < 2; mt++) {
        int r0 = row0 + wr * 32 + mt * 16 + g;
        #pragma unroll
        for (int nt = 0; nt < 8; nt++) {
            int col = col0 + wc * 64 + nt * 8 + t * 2;
            if (col < N) {
                *(float2*)(outp + (size_t)r0 * N + col) =
                    make_float2(acc[mt][nt][0], acc[mt][nt][1]);
                *(float2*)(outp + (size_t)(r0 + 8) * N + col) =
                    make_float2(acc[mt][nt][2], acc[mt][nt][3]);
            }
        }
    }
}

// ---------------- rmsnorm over D=1024, writes tf32-rounded fp32 ----------------
__global__ void __launch_bounds__(256) rmsnorm1024(const float* __restrict__ x,
                                                   const float* __restrict__ w,
                                                   float* __restrict__ outr) {
    int tok = blockIdx.x;
    int tid = threadIdx.x;
    const float4* xp = (const float4*)(x + (size_t)tok * DMODEL);
    float4 v = xp[tid];
    float ss = v.x * v.x + v.y * v.y + v.z * v.z + v.w * v.w;
    ss = blockReduceSum(ss);
    float rs = rsqrtf(ss * (1.0f / DMODEL) + EPSV);
    float4 wv = ((const float4*)w)[tid];
    float4 o;
    o.x = tf32r(v.x * rs * wv.x); o.y = tf32r(v.y * rs * wv.y);
    o.z = tf32r(v.z * rs * wv.z); o.w = tf32r(v.w * rs * wv.w);
    ((float4*)(outr + (size_t)tok * DMODEL))[tid] = o;
}

// ---------------- rmsnorm of (hidden + p0 + p1): writes x2 (fp32) + tf32-rounded ----------------
__global__ void __launch_bounds__(256) rmsnorm_sum3(const float* __restrict__ hid,
                                                    const float* __restrict__ p0,
                                                    const float* __restrict__ p1,
                                                    const float* __restrict__ w,
                                                    float* __restrict__ x2out,
                                                    float* __restrict__ outr) {
    int tok = blockIdx.x;
    int tid = threadIdx.x;
    size_t off = (size_t)tok * DMODEL;
    float4 a = ((const float4*)(hid + off))[tid];
    float4 b = ((const float4*)(p0  + off))[tid];
    float4 c = ((const float4*)(p1  + off))[tid];
    float4 v;
    v.x = a.x + b.x + c.x; v.y = a.y + b.y + c.y;
    v.z = a.z + b.z + c.z; v.w = a.w + b.w + c.w;
    ((float4*)(x2out + off))[tid] = v;
    float ss = v.x * v.x + v.y * v.y + v.z * v.z + v.w * v.w;
    ss = blockReduceSum(ss);
    float rs = rsqrtf(ss * (1.0f / DMODEL) + EPSV);
    float4 wv = ((const float4*)w)[tid];
    float4 o;
    o.x = tf32r(v.x * rs * wv.x); o.y = tf32r(v.y * rs * wv.y);
    o.z = tf32r(v.z * rs * wv.z); o.w = tf32r(v.w * rs * wv.w);
    ((float4*)(outr + off))[tid] = o;
}

// ---------------- final residual: out = x2 + p0 + p1 ----------------
__global__ void __launch_bounds__(256) add3(const float* __restrict__ x2,
                                            const float* __restrict__ p0,
                                            const float* __restrict__ p1,
                                            float* __restrict__ out, int n4) {
    int i = blockIdx.x * 256 + threadIdx.x;
    if (i < n4) {
        float4 a = ((const float4*)x2)[i];
        float4 b = ((const float4*)p0)[i];
        float4 c = ((const float4*)p1)[i];
        float4 v;
        v.x = a.x + b.x + c.x; v.y = a.y + b.y + c.y;
        v.z = a.z + b.z + c.z; v.w = a.w + b.w + c.w;
        ((float4*)out)[i] = v;
    }
}

// ---------------- swiglu + tf32 round: ddr = round(silu(g) * u) ----------------
__global__ void __launch_bounds__(256) swiglu_cvt(const float* __restrict__ g,
                                                  const float* __restrict__ u,
                                                  float* __restrict__ outr, int n4) {
    int i = blockIdx.x * 256 + threadIdx.x;
    if (i < n4) {
        float4 gv = ((const float4*)g)[i];
        float4 uv = ((const float4*)u)[i];
        float4 v;
        v.x = tf32r(siluf(gv.x) * uv.x); v.y = tf32r(siluf(gv.y) * uv.y);
        v.z = tf32r(siluf(gv.z) * uv.z); v.w = tf32r(siluf(gv.w) * uv.w);
        ((float4*)outr)[i] = v;
    }
}

// ---------------- gated rmsnorm over D_INNER=2048, writes tf32-rounded ----------------
__global__ void __launch_bounds__(256) gated_rmsnorm(const float* __restrict__ y,
                                                     const float* __restrict__ Z,
                                                     const float* __restrict__ w,
                                                     float* __restrict__ outr) {
    int tok = blockIdx.x;
    int tid = threadIdx.x;
    const float4* yp = (const float4*)(y + (size_t)tok * DINNER);
    const float4* zp = (const float4*)(Z + (size_t)tok * DINPROJ);
    float4 v[2];
    float ss = 0.f;
    #pragma unroll
    for (int q = 0; q < 2; q++) {
        float4 yv = yp[tid + q * 256];
        float4 zv = zp[tid + q * 256];
        float4 tt;
        tt.x = yv.x * siluf(zv.x); tt.y = yv.y * siluf(zv.y);
        tt.z = yv.z * siluf(zv.z); tt.w = yv.w * siluf(zv.w);
        v[q] = tt;
        ss += tt.x * tt.x + tt.y * tt.y + tt.z * tt.z + tt.w * tt.w;
    }
    ss = blockReduceSum(ss);
    float rs = rsqrtf(ss * (1.0f / DINNER) + EPSV);
    #pragma unroll
    for (int q = 0; q < 2; q++) {
        float4 wv = ((const float4*)w)[tid + q * 256];
        float4 o;
        o.x = tf32r(v[q].x * rs * wv.x); o.y = tf32r(v[q].y * rs * wv.y);
        o.z = tf32r(v[q].z * rs * wv.z); o.w = tf32r(v[q].w * rs * wv.w);
        ((float4*)(outr + (size_t)tok * DINNER))[tid + q * 256] = o;
    }
}

// ---------------- causal depthwise conv (width 4) + silu ----------------
__global__ void __launch_bounds__(256) conv_silu(const float* __restrict__ Z,
                                                 const float* __restrict__ cw,
                                                 const float* __restrict__ cb,
                                                 float* __restrict__ out) {
    int c   = blockIdx.x * 256 + threadIdx.x;
    int tok = blockIdx.y;
    if (c >= CONVDIM) return;
    int l = tok & (SEQLEN - 1);
    float w0 = cw[c * 4 + 0], w1 = cw[c * 4 + 1], w2 = cw[c * 4 + 2], w3 = cw[c * 4 + 3];
    const float* zc = Z + (size_t)tok * DINPROJ + DINNER + c;
    float acc = cb[c];
    acc += zc[0] * w3;
    if (l >= 1) acc += zc[-(ptrdiff_t)DINPROJ]     * w2;
    if (l >= 2) acc += zc[-(ptrdiff_t)DINPROJ * 2] * w1;
    if (l >= 3) acc += zc[-(ptrdiff_t)DINPROJ * 3] * w0;
    out[(size_t)tok * CONVDIM + c] = siluf(acc);
}

// ---------------- sequential SSM scan: 8-way p-split, 512 blocks ----------------
__global__ void __launch_bounds__(128) ssm_scan(const float* __restrict__ xBC,
                                                const float* __restrict__ Z,
                                                const float* __restrict__ dt_bias,
                                                const float* __restrict__ A_log,
                                                const float* __restrict__ Dp,
                                                float* __restrict__ y) {
    int bid   = blockIdx.x;          // 512 = b(2) * h(32) * oct(8)
    int b     = bid >> 8;
    int h     = (bid >> 3) & 31;
    int oct   = bid & 7;
    int pbase = oct * 8;
    int t     = threadIdx.x;

    __shared__ float s_dtx[2][2][8];
    __shared__ float s_x[2][2][8];
    __shared__ float s_red[2][8][144];

    float hs[8];
    #pragma unroll
    for (int p = 0; p < 8; p++) hs[p] = 0.f;

    float Ahv = -__expf(A_log[h]);
    float dbh = dt_bias[h];
    float Dh  = Dp[h];
    int   rp  = t >> 4;
    int   ri  = t & 15;

    const float* xrow  = xBC + (size_t)b * SEQLEN * CONVDIM;
    const float* dtrow = Z + (size_t)b * SEQLEN * DINPROJ + (DINPROJ - NHEADS) + h;
    float*       yrow  = y + (size_t)b * SEQLEN * DINNER + h * HEADDIM + pbase;

    float Bv[2], Cv[2], dAc[2];
    float B1[2], C1[2], dt1[2], x1v[2];

    #pragma unroll
    for (int q = 0; q < 2; q++) {
        const float* xr = xrow + (size_t)q * CONVDIM;
        Bv[q] = xr[DINNER + t];
        Cv[q] = xr[DINNER + DSTATE + t];
        float dts = dtrow[(size_t)q * DINPROJ] + dbh;
        float dtv = (dts > 20.f) ? dts : __logf(1.f + __expf(dts));
        dAc[q] = __expf(dtv * Ahv);
        if (t < 8) {
            float x0 = xr[h * HEADDIM + pbase + t];
            s_dtx[0][q][t] = dtv * x0; s_x[0][q][t] = x0;
        }
    }
    #pragma unroll
    for (int q = 0; q < 2; q++) {
        const float* xr = xrow + (size_t)(2 + q) * CONVDIM;
        B1[q]  = xr[DINNER + t];
        C1[q]  = xr[DINNER + DSTATE + t];
        dt1[q] = dtrow[(size_t)(2 + q) * DINPROJ];
        x1v[q] = (t < 8) ? xr[h * HEADDIM + pbase + t] : 0.f;
    }
    __syncthreads();

    int cur = 0;
    for (int i = 0; i < SEQLEN / 2; i++) {
        int nxt = cur ^ 1;
        float dAn[2] = {0.f, 0.f};
        if (i < SEQLEN / 2 - 1) {
            #pragma unroll
            for (int q = 0; q < 2; q++) {
                float dts = dt1[q] + dbh;
                float dtv = (dts > 20.f) ? dts : __logf(1.f + __expf(dts));
                dAn[q] = __expf(dtv * Ahv);
                if (t < 8) { s_dtx[nxt][q][t] = dtv * x1v[q]; s_x[nxt][q][t] = x1v[q]; }
            }
        }
        #pragma unroll
        for (int q = 0; q < 2; q++) {
            float dAq = dAc[q], Bq = Bv[q], Cq = Cv[q];
            #pragma unroll
            for (int p = 0; p < 8; p++) {
                hs[p] = fmaf(hs[p], dAq, s_dtx[cur][q][p] * Bq);
                s_red[q][p][t] = hs[p] * Cq;
            }
        }
        __syncthreads();

        #pragma unroll
        for (int q = 0; q < 2; q++) {
            float sum = 0.f;
            #pragma unroll
            for (int k = 0; k < 8; k++) sum += s_red[q][rp][k * 16 + ri];
            #pragma unroll
            for (int o = 8; o; o >>= 1) sum += __shfl_xor_sync(0xffffffffu, sum, o, 16);
            if (ri == 0)
                yrow[(size_t)(2 * i + q) * DINNER + rp] = sum + Dh * s_x[cur][q][rp];
        }

        dAc[0] = dAn[0]; dAc[1] = dAn[1];
        Bv[0] = B1[0]; Bv[1] = B1[1];
        Cv[0] = C1[0]; Cv[1] = C1[1];
        if (i < SEQLEN / 2 - 2) {
            #pragma unroll
            for (int q = 0; q < 2; q++) {
                int s = 2 * i + 4 + q;
                const float* xr = xrow + (size_t)s * CONVDIM;
                B1[q]  = xr[DINNER + t];
                C1[q]  = xr[DINNER + DSTATE + t];
                dt1[q] = dtrow[(size_t)s * DINPROJ];
                x1v[q] = (t < 8) ? xr[h * HEADDIM + pbase + t] : 0.f;
            }
        }
        __syncthreads();
        cur = nxt;
    }
}

// ---------------- launch ----------------
extern "C" void kernel_launch(void* const* d_in, const int* in_sizes, int n_in,
                              void* d_out, int out_size) {
    const float* hidden     = (const float*)d_in[0];
    const float* norm_w     = (const float*)d_in[1];
    const float* in_proj_w  = (const float*)d_in[2];
    const float* conv_w     = (const float*)d_in[3];
    const float* conv_b     = (const float*)d_in[4];
    const float* dt_bias    = (const float*)d_in[5];
    const float* A_log      = (const float*)d_in[6];
    const float* Dvec       = (const float*)d_in[7];
    const float* ssm_norm_w = (const float*)d_in[8];
    const float* out_proj_w = (const float*)d_in[9];
    const float* post_norm_w= (const float*)d_in[10];
    const float* gate_w     = (const float*)d_in[11];
    const float* up_w       = (const float*)d_in[12];
    const float* down_w     = (const float*)d_in[13];
    float* out = (float*)d_out;

    float *Z, *xBC, *y, *x2, *gg, *uu;
    cudaGetSymbolAddress((void**)&Z,   g_Z);
    cudaGetSymbolAddress((void**)&xBC, g_xBC);
    cudaGetSymbolAddress((void**)&y,   g_y);
    cudaGetSymbolAddress((void**)&x2,  g_x2);
    cudaGetSymbolAddress((void**)&gg,  g_g);
    cudaGetSymbolAddress((void**)&uu,  g_u);

    float *x1r, *h2r, *y2r, *ddr;
    cudaGetSymbolAddress((void**)&x1r, g_x1r);
    cudaGetSymbolAddress((void**)&h2r, g_h2r);
    cudaGetSymbolAddress((void**)&y2r, g_y2r);
    cudaGetSymbolAddress((void**)&ddr, g_ddr);

    float *wir, *wor, *wgr, *wur, *wdr;
    cudaGetSymbolAddress((void**)&wir, g_wir);
    cudaGetSymbolAddress((void**)&wor, g_wor);
    cudaGetSymbolAddress((void**)&wgr, g_wgr);
    cudaGetSymbolAddress((void**)&wur, g_wur);
    cudaGetSymbolAddress((void**)&wdr, g_wdr);

    cudaFuncSetAttribute(gemm_tf32, cudaFuncAttributeMaxDynamicSharedMemorySize, GEMM_SMEM);

    const int nIn = DINPROJ * DMODEL / 4, nOut = DMODEL * DINNER / 4;
    const int nGU = INTERD * DMODEL / 4,  nDn  = DMODEL * INTERD / 4;

    // 0,1: weight tf32 rounding (2 merged launches)
    wcvt3<<<(nIn + nOut + nGU + 255) / 256, 256>>>(
        in_proj_w, wir, nIn, out_proj_w, wor, nOut, gate_w, wgr, nGU);
    wcvt3<<<(nGU + nDn + 255) / 256, 256>>>(
        up_w, wur, nGU, down_w, wdr, nDn, nullptr, nullptr, 0);

    // 2: pre-norm -> x1r (rounded)
    rmsnorm1024<<<NTOK, 256>>>(hidden, norm_w, x1r);
    // 3: in_proj -> Z
    gemm_tf32<<<dim3((DINPROJ + 127) / 128, NTOK / 128, 1), 256, GEMM_SMEM>>>(
        x1r, wir, nullptr, Z, nullptr, NTOK, DINPROJ, DMODEL, 1);
    // 4: causal conv + silu
    conv_silu<<<dim3((CONVDIM + 255) / 256, NTOK), 256>>>(Z, conv_w, conv_b, xBC);
    // 5: SSM scan (+ D skip)
    ssm_scan<<<512, 128>>>(xBC, Z, dt_bias, A_log, Dvec, y);
    // 6: gated rmsnorm -> y2r  (Z z-gate consumed; Z dead after)
    gated_rmsnorm<<<NTOK, 256>>>(y, Z, ssm_norm_w, y2r);
    // 7: out_proj split-K2 -> partials in Z scratch
    gemm_tf32<<<dim3(DMODEL / 128, NTOK / 128, 2), 256, GEMM_SMEM>>>(
        y2r, wor, nullptr, Z, nullptr, NTOK, DMODEL, DINNER, 2);
    // 8: x2 = hidden + p0 + p1; post-norm -> h2r
    rmsnorm_sum3<<<NTOK, 256>>>(hidden, Z, Z + (size_t)NTOK * DMODEL, post_norm_w, x2, h2r);
    // 9: gate & up fused in one launch (z selects weight/output)
    gemm_tf32<<<dim3((INTERD + 127) / 128, NTOK / 128, 2), 256, GEMM_SMEM>>>(
        h2r, wgr, wur, gg, uu, NTOK, INTERD, DMODEL, 1);
    // 10: swiglu + round -> ddr
    swiglu_cvt<<<(NTOK * INTERD / 4 + 255) / 256, 256>>>(
        gg, uu, ddr, NTOK * INTERD / 4);
    // 11: down proj split-K2 -> partials in gg scratch
    gemm_tf32<<<dim3(DMODEL / 128, NTOK / 128, 2), 256, GEMM_SMEM>>>(
        ddr, wdr, nullptr, gg, nullptr, NTOK, DMODEL, INTERD, 2);
    // 12: out = x2 + p0 + p1
    add3<<<(NTOK * DMODEL / 4 + 255) / 256, 256>>>(
        x2, gg, gg + (size_t)NTOK * DMODEL, out, NTOK * DMODEL / 4);
}